// round 11
// baseline (speedup 1.0000x reference)
#include <cuda_runtime.h>
#include <cfloat>

// Problem shape (fixed by reference): point_cloud [32, 262144, 3] fp32
static constexpr int NB       = 32;
static constexpr int NPTS     = 262144;
static constexpr int F_PER_B  = NPTS * 3;            // 786432 floats per batch
static constexpr int Q_PER_B  = F_PER_B / 4;         // 196608 float4 per batch

static constexpr int THREADS  = 256;
static constexpr int BLOCKS1  = 32;                  // pass-1 blocks/batch
static constexpr int CHUNK1   = Q_PER_B / BLOCKS1;       // 6144 float4/block
static constexpr int ITER1    = CHUNK1 / (3 * THREADS);  // 8
static constexpr int BLOCKS2  = 64;                  // pass-2 blocks/batch
static constexpr int CHUNK2   = Q_PER_B / BLOCKS2;       // 3072 float4/block
static constexpr int NSTAGE   = CHUNK2 / THREADS;        // 12 stages of 256 float4
static constexpr int STAGES   = 6;                   // cp.async ring depth (24 KB smem)
static constexpr int INFLIGHT = 4;                   // wait_group bound -> 5 stages in flight

// Per-(batch, quantity, block) partials; written unconditionally each launch
// -> no init kernel, no atomics, graph-replay safe.
// Quantity: 0..2 = min(x,y,z), 3..5 = max(x,y,z).
__device__ float g_part[NB][6][BLOCKS1];

// Component bookkeeping: float4 at index idx has components
// ((idx)%3,(idx+1)%3,(idx+2)%3,(idx)%3). All chunk bases are multiples of 3,
// and both the pass-1 iteration stride and the pass-2 stage stride are
// THREADS=256 ≡ 1 (mod 3): with r = tid%3, pass-1 sub-iter u / pass-2 stage k
// has leading component (r+u)%3 / (r+k)%3 — all selection static after
// pre-rotating accumulators/constants by r.

// ───────────────── Pass 1: per-batch per-coord min/max partials ─────────────
__global__ void __launch_bounds__(THREADS)
minmax_kernel(const float4* __restrict__ p) {
    const int b = blockIdx.y;
    const float4* pb = p + (size_t)b * Q_PER_B + blockIdx.x * CHUNK1;
    const int tid = threadIdx.x;
    const int r = tid % 3;

    float mnA0 =  FLT_MAX, mnA1 =  FLT_MAX, mnA2 =  FLT_MAX;
    float mxA0 = -FLT_MAX, mxA1 = -FLT_MAX, mxA2 = -FLT_MAX;

    #pragma unroll 4
    for (int ko = 0; ko < ITER1; ko++) {
        const float4 a = pb[(ko * 3 + 0) * THREADS + tid];  // default policy: fills L2 for pass 2
        const float4 d = pb[(ko * 3 + 1) * THREADS + tid];
        const float4 c = pb[(ko * 3 + 2) * THREADS + tid];
        mnA0 = fminf(mnA0, fminf(a.x, a.w)); mxA0 = fmaxf(mxA0, fmaxf(a.x, a.w));
        mnA1 = fminf(mnA1, a.y);             mxA1 = fmaxf(mxA1, a.y);
        mnA2 = fminf(mnA2, a.z);             mxA2 = fmaxf(mxA2, a.z);
        mnA1 = fminf(mnA1, fminf(d.x, d.w)); mxA1 = fmaxf(mxA1, fmaxf(d.x, d.w));
        mnA2 = fminf(mnA2, d.y);             mxA2 = fmaxf(mxA2, d.y);
        mnA0 = fminf(mnA0, d.z);             mxA0 = fmaxf(mxA0, d.z);
        mnA2 = fminf(mnA2, fminf(c.x, c.w)); mxA2 = fmaxf(mxA2, fmaxf(c.x, c.w));
        mnA0 = fminf(mnA0, c.y);             mxA0 = fmaxf(mxA0, c.y);
        mnA1 = fminf(mnA1, c.z);             mxA1 = fmaxf(mxA1, c.z);
    }

    // Un-rotate: comp k lives in slot (k - r + 3) % 3
    float mn0, mn1, mn2, mx0, mx1, mx2;
    if (r == 0)      { mn0 = mnA0; mn1 = mnA1; mn2 = mnA2; mx0 = mxA0; mx1 = mxA1; mx2 = mxA2; }
    else if (r == 1) { mn0 = mnA2; mn1 = mnA0; mn2 = mnA1; mx0 = mxA2; mx1 = mxA0; mx2 = mxA1; }
    else             { mn0 = mnA1; mn1 = mnA2; mn2 = mnA0; mx0 = mxA1; mx1 = mxA2; mx2 = mxA0; }

    #pragma unroll
    for (int off = 16; off > 0; off >>= 1) {
        mn0 = fminf(mn0, __shfl_xor_sync(0xFFFFFFFFu, mn0, off));
        mn1 = fminf(mn1, __shfl_xor_sync(0xFFFFFFFFu, mn1, off));
        mn2 = fminf(mn2, __shfl_xor_sync(0xFFFFFFFFu, mn2, off));
        mx0 = fmaxf(mx0, __shfl_xor_sync(0xFFFFFFFFu, mx0, off));
        mx1 = fmaxf(mx1, __shfl_xor_sync(0xFFFFFFFFu, mx1, off));
        mx2 = fmaxf(mx2, __shfl_xor_sync(0xFFFFFFFFu, mx2, off));
    }

    __shared__ float s[6][THREADS / 32];
    const int w = tid >> 5, lane = tid & 31;
    if (lane == 0) {
        s[0][w] = mn0; s[1][w] = mn1; s[2][w] = mn2;
        s[3][w] = mx0; s[4][w] = mx1; s[5][w] = mx2;
    }
    __syncthreads();

    if (tid < 6) {
        float v = s[tid][0];
        if (tid < 3) {
            #pragma unroll
            for (int k = 1; k < THREADS / 32; k++) v = fminf(v, s[tid][k]);
        } else {
            #pragma unroll
            for (int k = 1; k < THREADS / 32; k++) v = fmaxf(v, s[tid][k]);
        }
        g_part[b][tid][blockIdx.x] = v;
    }
}

// ───────────────── Pass 2: cp.async-staged voxelization ─────────────────────
// Each thread stages its own float4 per stage via cp.async (LDGSTS.128) into a
// 6-deep SMEM ring and self-consumes it -> up to 5 stages (80B) in flight per
// thread with ~32-reg occupancy. No __syncthreads in the main loop: thread i
// only ever reads buf[slot][i], which it copied itself.
__device__ __forceinline__ void cp_async16(void* smem_dst, const void* gmem_src) {
    unsigned saddr = (unsigned)__cvta_generic_to_shared(smem_dst);
    asm volatile("cp.async.cg.shared.global [%0], [%1], 16;" :: "r"(saddr), "l"(gmem_src));
}
__device__ __forceinline__ void cp_commit() {
    asm volatile("cp.async.commit_group;");
}
__device__ __forceinline__ void cp_wait4() {
    asm volatile("cp.async.wait_group %0;" :: "n"(INFLIGHT));
}

__global__ void __launch_bounds__(THREADS)
voxel_kernel(const float4* __restrict__ p, float4* __restrict__ out) {
    const int b = blockIdx.y;
    const int tid = threadIdx.x;

    __shared__ float4 buf[STAGES][THREADS];   // 24 KB ring
    __shared__ float  cst[6];

    const size_t base = (size_t)b * Q_PER_B + blockIdx.x * CHUNK2;
    const float4* pb = p + base;
    float4* ob = out + base;

    // Kick off the first STAGES-1 stage copies immediately (hide latency
    // behind the constants prologue below).
    #pragma unroll
    for (int k = 0; k < STAGES - 1; k++) {
        cp_async16(&buf[k][tid], &pb[k * THREADS + tid]);
        cp_commit();
    }

    // Prologue: warps 0..5 each reduce the 32 per-block partials.
    {
        const int w = tid >> 5, lane = tid & 31;
        if (w < 6) {
            float v = g_part[b][w][lane];
            if (w < 3) {
                #pragma unroll
                for (int off = 16; off > 0; off >>= 1)
                    v = fminf(v, __shfl_xor_sync(0xFFFFFFFFu, v, off));
            } else {
                #pragma unroll
                for (int off = 16; off > 0; off >>= 1)
                    v = fmaxf(v, __shfl_xor_sync(0xFFFFFFFFu, v, off));
            }
            if (lane == 0) cst[w] = v;
        }
    }
    __syncthreads();

    // Same RN /40 as reference, then reciprocal-multiply per point
    // (rel err << 1e-3 threshold).
    const float mnc[3]  = { cst[0], cst[1], cst[2] };
    const float invc[3] = { 1.0f / ((cst[3] - cst[0]) / 40.0f),
                            1.0f / ((cst[4] - cst[1]) / 40.0f),
                            1.0f / ((cst[5] - cst[2]) / 40.0f) };
    // Pre-rotate by r = tid%3: slot s covers component (r+s)%3.
    const int r = tid % 3;
    float mnR[3], ivR[3];
    #pragma unroll
    for (int s2 = 0; s2 < 3; s2++) {
        const int c = (r + s2) < 3 ? (r + s2) : (r + s2 - 3);
        mnR[s2] = mnc[c];
        ivR[s2] = invc[c];
    }

    // Main loop: stage k has leading component (r+k)%3 -> rotated slot k%3.
    #pragma unroll
    for (int k = 0; k < NSTAGE; k++) {
        // Keep the pipeline fed (empty commit keeps group accounting uniform).
        if (k + STAGES - 1 < NSTAGE)
            cp_async16(&buf[(k + STAGES - 1) % STAGES][tid],
                       &pb[(k + STAGES - 1) * THREADS + tid]);
        cp_commit();
        cp_wait4();                       // stages <= k complete for this thread

        const float4 v = buf[k % STAGES][tid];
        const int u0 = k % 3, u1 = (k + 1) % 3, u2 = (k + 2) % 3;

        float4 res;
        res.x = floorf((v.x - mnR[u0]) * ivR[u0]);
        res.y = floorf((v.y - mnR[u1]) * ivR[u1]);
        res.z = floorf((v.z - mnR[u2]) * ivR[u2]);
        res.w = floorf((v.w - mnR[u0]) * ivR[u0]);

        __stcs(&ob[k * THREADS + tid], res);
    }
}

extern "C" void kernel_launch(void* const* d_in, const int* in_sizes, int n_in,
                              void* d_out, int out_size) {
    const float4* p = (const float4*)d_in[0];
    float4* o = (float4*)d_out;

    minmax_kernel<<<dim3(BLOCKS1, NB), THREADS>>>(p);
    voxel_kernel<<<dim3(BLOCKS2, NB), THREADS>>>(p, o);
}